// round 17
// baseline (speedup 1.0000x reference)
#include <cuda_runtime.h>
#include <cuda_fp16.h>
#include <cstdint>

#define BB 8
#define TT 256
#define UU 64
#define ENC_DIM 512
#define PRED_DIM 640
#define JDIM 512
#define VOCAB 1024
#define MROWS (BB * TT * UU)   // 131072

// ---------------------------------------------------------------------------
// Device scratch
// ---------------------------------------------------------------------------
__device__ float g_enc_p[BB * TT * JDIM];               // 4 MB
__device__ float g_pred_p[BB * UU * JDIM];              // 1 MB
__device__ __half g_a[(size_t)MROWS * JDIM];            // 128 MB (fp16 tanh plane)
__device__ __half g_wt[VOCAB * JDIM];                   // 1 MB  (W_joint^T fp16)
__device__ __half g_enc_h[BB * TT * ENC_DIM];           // 2 MB
__device__ __half g_pred_h[BB * UU * PRED_DIM];         // 0.65 MB
__device__ __half g_wenc_t[JDIM * ENC_DIM];             // [n,k] fp16
__device__ __half g_wpred_t[JDIM * PRED_DIM];           // [n,k] fp16

// ---------------------------------------------------------------------------
// Helpers
// ---------------------------------------------------------------------------
__device__ __forceinline__ uint32_t smem_u32(const void* p) {
    uint32_t a;
    asm("{ .reg .u64 t; cvta.to.shared.u64 t, %1; cvt.u32.u64 %0, t; }" : "=r"(a) : "l"(p));
    return a;
}
#define CP16(dst, src) \
    asm volatile("cp.async.cg.shared.global [%0], [%1], 16;" :: "r"((uint32_t)(dst)), "l"(src) : "memory")
#define CP_COMMIT() asm volatile("cp.async.commit_group;" ::: "memory")

#define LDSM4(r, addr) \
    asm volatile("ldmatrix.sync.aligned.m8n8.x4.shared.b16 {%0,%1,%2,%3}, [%4];" \
                 : "=r"((r)[0]), "=r"((r)[1]), "=r"((r)[2]), "=r"((r)[3]) : "r"(addr))

// f32-accumulate mma (projections)
#define MMA16816(acc, a, b0, b1) \
    asm volatile("mma.sync.aligned.m16n8k16.row.col.f32.f16.f16.f32 " \
                 "{%0,%1,%2,%3},{%4,%5,%6,%7},{%8,%9},{%0,%1,%2,%3};" \
                 : "+f"((acc)[0]), "+f"((acc)[1]), "+f"((acc)[2]), "+f"((acc)[3]) \
                 : "r"((a)[0]), "r"((a)[1]), "r"((a)[2]), "r"((a)[3]), "r"(b0), "r"(b1))

// f16-accumulate mma (joint): D,C are 2 regs of f16x2
#define MMA16816H(acch, a, b0, b1) \
    asm volatile("mma.sync.aligned.m16n8k16.row.col.f16.f16.f16.f16 " \
                 "{%0,%1},{%2,%3,%4,%5},{%6,%7},{%0,%1};" \
                 : "+r"((acch)[0]), "+r"((acch)[1]) \
                 : "r"((a)[0]), "r"((a)[1]), "r"((a)[2]), "r"((a)[3]), "r"(b0), "r"(b1))

// HW tanh (MUFU.TANH)
__device__ __forceinline__ float tanh_hw(float x) {
    float y;
    asm("tanh.approx.f32 %0, %1;" : "=f"(y) : "f"(x));
    return y;
}
__device__ __forceinline__ uint32_t pack2h(__half a, __half b) {
    return (uint32_t)__half_as_ushort(a) | ((uint32_t)__half_as_ushort(b) << 16);
}

// ---------------------------------------------------------------------------
// convert: fp16-quantize inputs and transpose weight matrices.
// ---------------------------------------------------------------------------
#define S1 (BB * TT * ENC_DIM)
#define S2 (BB * UU * PRED_DIM)
#define S3 (JDIM * ENC_DIM)
#define S4 (JDIM * PRED_DIM)
#define S5 (VOCAB * JDIM)
#define CONV_TOTAL (S1 + S2 + S3 + S4 + S5)   // 2490368

__global__ __launch_bounds__(256) void convert_kernel(
    const float* __restrict__ enc_out, const float* __restrict__ pred_out,
    const float* __restrict__ W_enc, const float* __restrict__ W_pred,
    const float* __restrict__ W_joint)
{
    int gid = blockIdx.x * 256 + threadIdx.x;
    if (gid < S1) {
        g_enc_h[gid] = __float2half_rn(enc_out[gid]);
    } else if ((gid -= S1) < S2) {
        g_pred_h[gid] = __float2half_rn(pred_out[gid]);
    } else if ((gid -= S2) < S3) {
        int n = gid >> 9, k = gid & 511;
        g_wenc_t[gid] = __float2half_rn(W_enc[k * JDIM + n]);
    } else if ((gid -= S3) < S4) {
        int n = gid / PRED_DIM, k = gid - n * PRED_DIM;
        g_wpred_t[gid] = __float2half_rn(W_pred[k * JDIM + n]);
    } else if ((gid -= S4) < S5) {
        int v = gid >> 9, k = gid & 511;
        g_wt[gid] = __float2half_rn(W_joint[k * VOCAB + v]);
    }
}

// ---------------------------------------------------------------------------
// Shared HMMA tile config
// ---------------------------------------------------------------------------
#define BM 128
#define BN 128
#define BK 64
#define NPIPE 3
#define ASTRIDE 144
#define A_PLANE (BM * ASTRIDE)          // 18432
#define B_PLANE (BN * ASTRIDE)          // 18432
#define STG_BYTES (A_PLANE + B_PLANE)   // 36864
#define OFF_A 0
#define OFF_B A_PLANE
#define HMMA_SMEM (NPIPE * STG_BYTES + 1024)  // 111616

__device__ __forceinline__ void load_stage_g(uint32_t sbase,
                                             const __half* __restrict__ A,
                                             const __half* __restrict__ Bt,
                                             int K, int k0, int m0, int n0, int tid) {
#pragma unroll
    for (int it = 0; it < 4; it++) {
        int c = tid + it * 256;
        int row = c >> 3, cq = c & 7;
        CP16(sbase + OFF_A + row * ASTRIDE + cq * 16,
             A + (size_t)(m0 + row) * K + k0 + cq * 8);
    }
#pragma unroll
    for (int it = 0; it < 4; it++) {
        int c = tid + it * 256;
        int row = c >> 3, cq = c & 7;
        CP16(sbase + OFF_B + row * ASTRIDE + cq * 16,
             Bt + (size_t)(n0 + row) * K + k0 + cq * 8);
    }
}

// ---------------------------------------------------------------------------
// HMMA projections (f32 accumulate; small, unchanged from R16)
// ---------------------------------------------------------------------------
__global__ __launch_bounds__(256, 2) void proj_hmma_kernel(
    const float* __restrict__ b_enc, const float* __restrict__ b_pred)
{
    extern __shared__ char dsm[];
    const uint32_t sb = smem_u32(dsm);
    float* sbias = (float*)(dsm + NPIPE * STG_BYTES);

    const int tid = threadIdx.x;
    const int l   = tid & 31;
    const int w   = tid >> 5;
    const int mw  = w & 1;
    const int nw  = w >> 1;
    const int bid = blockIdx.x;

    const __half* A;
    const __half* Bt;
    const float* bias;
    float* C;
    int K, q;
    if (bid < 64) {
        A = g_enc_h;  Bt = g_wenc_t;  bias = b_enc;  C = g_enc_p;
        K = ENC_DIM;  q = bid;
    } else {
        A = g_pred_h; Bt = g_wpred_t; bias = b_pred; C = g_pred_p;
        K = PRED_DIM; q = bid - 64;
    }
    const int m0 = (q >> 2) * BM;
    const int n0 = (q & 3) * BN;
    const int nstg = K / BK;

    if (tid < BN) sbias[tid] = bias[n0 + tid];

    load_stage_g(sb + 0 * STG_BYTES, A, Bt, K, 0 * BK, m0, n0, tid); CP_COMMIT();
    load_stage_g(sb + 1 * STG_BYTES, A, Bt, K, 1 * BK, m0, n0, tid); CP_COMMIT();

    float acc[4][4][4];
#pragma unroll
    for (int i = 0; i < 4; i++)
#pragma unroll
        for (int j = 0; j < 4; j++)
#pragma unroll
            for (int t = 0; t < 4; t++) acc[i][j][t] = 0.0f;

    const uint32_t a_off = (uint32_t)((mw * 64 + (l & 15)) * ASTRIDE + (l >> 4) * 16);
    const uint32_t b_off = (uint32_t)((nw * 32 + ((l >> 4) << 3) + (l & 7)) * ASTRIDE
                                      + ((l >> 3) & 1) * 16);

    for (int s = 0; s < nstg; s++) {
        asm volatile("cp.async.wait_group 1;" ::: "memory");
        __syncthreads();

        const uint32_t stg = sb + (s % NPIPE) * STG_BYTES;
        uint32_t aa[2][4][4], bb[2][2][4];

#pragma unroll
        for (int kk = 0; kk < 2; kk++) {
#pragma unroll
            for (int mf = 0; mf < 4; mf++)
                LDSM4(aa[kk][mf], stg + OFF_A + a_off + kk * 32 + mf * 16 * ASTRIDE);
#pragma unroll
            for (int np = 0; np < 2; np++)
                LDSM4(bb[kk][np], stg + OFF_B + b_off + kk * 32 + np * 16 * ASTRIDE);
        }
        if (s + 2 < nstg)
            load_stage_g(sb + ((s + 2) % NPIPE) * STG_BYTES, A, Bt, K, (s + 2) * BK, m0, n0, tid);
        CP_COMMIT();
#pragma unroll
        for (int kk = 0; kk < 2; kk++)
#pragma unroll
            for (int mf = 0; mf < 4; mf++)
#pragma unroll
                for (int np = 0; np < 2; np++) {
                    MMA16816(acc[mf][np * 2 + 0], aa[kk][mf], bb[kk][np][0], bb[kk][np][1]);
                    MMA16816(acc[mf][np * 2 + 1], aa[kk][mf], bb[kk][np][2], bb[kk][np][3]);
                }

#pragma unroll
        for (int kk = 0; kk < 2; kk++) {
#pragma unroll
            for (int mf = 0; mf < 4; mf++)
                LDSM4(aa[kk][mf], stg + OFF_A + a_off + 64 + kk * 32 + mf * 16 * ASTRIDE);
#pragma unroll
            for (int np = 0; np < 2; np++)
                LDSM4(bb[kk][np], stg + OFF_B + b_off + 64 + kk * 32 + np * 16 * ASTRIDE);
        }
#pragma unroll
        for (int kk = 0; kk < 2; kk++)
#pragma unroll
            for (int mf = 0; mf < 4; mf++)
#pragma unroll
                for (int np = 0; np < 2; np++) {
                    MMA16816(acc[mf][np * 2 + 0], aa[kk][mf], bb[kk][np][0], bb[kk][np][1]);
                    MMA16816(acc[mf][np * 2 + 1], aa[kk][mf], bb[kk][np][2], bb[kk][np][3]);
                }
    }

#pragma unroll
    for (int mf = 0; mf < 4; mf++) {
        const int r0 = m0 + mw * 64 + mf * 16 + (l >> 2);
#pragma unroll
        for (int nf = 0; nf < 4; nf++) {
            const int c  = n0 + nw * 32 + nf * 8 + ((l & 3) << 1);
            const float2 b2 = *(const float2*)&sbias[c - n0];
            float2 o0, o1;
            o0.x = acc[mf][nf][0] + b2.x;
            o0.y = acc[mf][nf][1] + b2.y;
            o1.x = acc[mf][nf][2] + b2.x;
            o1.y = acc[mf][nf][3] + b2.y;
            *(float2*)&C[(size_t)r0 * JDIM + c]       = o0;
            *(float2*)&C[(size_t)(r0 + 8) * JDIM + c] = o1;
        }
    }
}

// ---------------------------------------------------------------------------
// prep_A v3 (unchanged)
// ---------------------------------------------------------------------------
__global__ __launch_bounds__(256) void prep_a_kernel() {
    int gid = blockIdx.x * 256 + threadIdx.x;
    int bt = gid >> 10;
    int r  = gid & 1023;
    int u  = r >> 6;
    int k8 = (r & 63) << 3;
    int b  = bt >> 8;

    const float4* e = (const float4*)(g_enc_p + (size_t)bt * JDIM + k8);
    const float4 e0 = e[0], e1 = e[1];

    float4 p[4][2];
    const float4* pb = (const float4*)(g_pred_p + ((size_t)(b * UU)) * JDIM + k8);
#pragma unroll
    for (int j = 0; j < 4; j++) {
        const float4* pr = pb + (size_t)(u + j * 16) * (JDIM / 4);
        p[j][0] = pr[0];
        p[j][1] = pr[1];
    }

#pragma unroll
    for (int j = 0; j < 4; j++) {
        __half h[8];
        h[0] = __float2half_rn(tanh_hw(e0.x + p[j][0].x));
        h[1] = __float2half_rn(tanh_hw(e0.y + p[j][0].y));
        h[2] = __float2half_rn(tanh_hw(e0.z + p[j][0].z));
        h[3] = __float2half_rn(tanh_hw(e0.w + p[j][0].w));
        h[4] = __float2half_rn(tanh_hw(e1.x + p[j][1].x));
        h[5] = __float2half_rn(tanh_hw(e1.y + p[j][1].y));
        h[6] = __float2half_rn(tanh_hw(e1.z + p[j][1].z));
        h[7] = __float2half_rn(tanh_hw(e1.w + p[j][1].w));
        uint4 H;
        H.x = pack2h(h[0], h[1]); H.y = pack2h(h[2], h[3]);
        H.z = pack2h(h[4], h[5]); H.w = pack2h(h[6], h[7]);
        *(uint4*)(g_a + (size_t)(bt * UU + u + j * 16) * JDIM + k8) = H;
    }
}

// ---------------------------------------------------------------------------
// Joint GEMM with f16 accumulators + periodic f32 flush.
// BM=128, BN=128, BK=64, 256 threads, warp tile 64x32, NPIPE=3.
// accH (f16x2) accumulates a K=128 window (2 stages, 8-mma chains starting
// from zero); flushed into f32 accF every 2 stages. If f16-acc HMMA is
// full-rate (rt=8 vs rt=16 for f32-acc), tensor time halves.
// ---------------------------------------------------------------------------
#define NSTG 8

__global__ __launch_bounds__(256, 1) void joint_kernel(
    const float* __restrict__ bias, float* __restrict__ out)
{
    extern __shared__ char dsm[];
    const uint32_t sb = smem_u32(dsm);
    float* sbias = (float*)(dsm + NPIPE * STG_BYTES);

    const int tid = threadIdx.x;
    const int l   = tid & 31;
    const int w   = tid >> 5;
    const int mw  = w & 1;
    const int nw  = w >> 1;
    const int bid = blockIdx.x;
    const int n0  = (bid & 7) * BN;
    const int m0  = (bid >> 3) * BM;

    if (tid < BN) sbias[tid] = bias[n0 + tid];

    load_stage_g(sb + 0 * STG_BYTES, g_a, g_wt, JDIM, 0 * BK, m0, n0, tid); CP_COMMIT();
    load_stage_g(sb + 1 * STG_BYTES, g_a, g_wt, JDIM, 1 * BK, m0, n0, tid); CP_COMMIT();

    float acc[4][4][4];
#pragma unroll
    for (int i = 0; i < 4; i++)
#pragma unroll
        for (int j = 0; j < 4; j++)
#pragma unroll
            for (int q = 0; q < 4; q++) acc[i][j][q] = 0.0f;

    uint32_t accH[4][4][2];
#pragma unroll
    for (int i = 0; i < 4; i++)
#pragma unroll
        for (int j = 0; j < 4; j++) { accH[i][j][0] = 0u; accH[i][j][1] = 0u; }

    const uint32_t a_off = (uint32_t)((mw * 64 + (l & 15)) * ASTRIDE + (l >> 4) * 16);
    const uint32_t b_off = (uint32_t)((nw * 32 + ((l >> 4) << 3) + (l & 7)) * ASTRIDE
                                      + ((l >> 3) & 1) * 16);

    for (int s = 0; s < NSTG; s++) {
        asm volatile("cp.async.wait_group 1;" ::: "memory");
        __syncthreads();

        const uint32_t stg = sb + (s % NPIPE) * STG_BYTES;
        uint32_t aa[2][4][4], bb[2][2][4];

        // ---- kk-pair 0 ----
#pragma unroll
        for (int kk = 0; kk < 2; kk++) {
#pragma unroll
            for (int mf = 0; mf < 4; mf++)
                LDSM4(aa[kk][mf], stg + OFF_A + a_off + kk * 32 + mf * 16 * ASTRIDE);
#pragma unroll
            for (int np = 0; np < 2; np++)
                LDSM4(bb[kk][np], stg + OFF_B + b_off + kk * 32 + np * 16 * ASTRIDE);
        }
        if (s + 2 < NSTG)
            load_stage_g(sb + ((s + 2) % NPIPE) * STG_BYTES, g_a, g_wt, JDIM, (s + 2) * BK, m0, n0, tid);
        CP_COMMIT();
#pragma unroll
        for (int kk = 0; kk < 2; kk++)
#pragma unroll
            for (int mf = 0; mf < 4; mf++)
#pragma unroll
                for (int np = 0; np < 2; np++) {
                    MMA16816H(accH[mf][np * 2 + 0], aa[kk][mf], bb[kk][np][0], bb[kk][np][1]);
                    MMA16816H(accH[mf][np * 2 + 1], aa[kk][mf], bb[kk][np][2], bb[kk][np][3]);
                }

        // ---- kk-pair 1 ----
#pragma unroll
        for (int kk = 0; kk < 2; kk++) {
#pragma unroll
            for (int mf = 0; mf < 4; mf++)
                LDSM4(aa[kk][mf], stg + OFF_A + a_off + 64 + kk * 32 + mf * 16 * ASTRIDE);
#pragma unroll
            for (int np = 0; np < 2; np++)
                LDSM4(bb[kk][np], stg + OFF_B + b_off + 64 + kk * 32 + np * 16 * ASTRIDE);
        }
#pragma unroll
        for (int kk = 0; kk < 2; kk++)
#pragma unroll
            for (int mf = 0; mf < 4; mf++)
#pragma unroll
                for (int np = 0; np < 2; np++) {
                    MMA16816H(accH[mf][np * 2 + 0], aa[kk][mf], bb[kk][np][0], bb[kk][np][1]);
                    MMA16816H(accH[mf][np * 2 + 1], aa[kk][mf], bb[kk][np][2], bb[kk][np][3]);
                }

        // flush f16 window into f32 every 2 stages (K=128 per window)
        if (s & 1) {
#pragma unroll
            for (int mf = 0; mf < 4; mf++)
#pragma unroll
                for (int nf = 0; nf < 4; nf++) {
#pragma unroll
                    for (int q = 0; q < 2; q++) {
                        __half2 h = *(__half2*)&accH[mf][nf][q];
                        float2 f = __half22float2(h);
                        acc[mf][nf][q * 2 + 0] += f.x;
                        acc[mf][nf][q * 2 + 1] += f.y;
                        accH[mf][nf][q] = 0u;
                    }
                }
        }
    }

    // epilogue: add bias, direct stores
#pragma unroll
    for (int mf = 0; mf < 4; mf++) {
        const int r0 = m0 + mw * 64 + mf * 16 + (l >> 2);
#pragma unroll
        for (int nf = 0; nf < 4; nf++) {
            const int c  = n0 + nw * 32 + nf * 8 + ((l & 3) << 1);
            const float2 b2 = *(const float2*)&sbias[c - n0];
            float2 o0, o1;
            o0.x = acc[mf][nf][0] + b2.x;
            o0.y = acc[mf][nf][1] + b2.y;
            o1.x = acc[mf][nf][2] + b2.x;
            o1.y = acc[mf][nf][3] + b2.y;
            *(float2*)&out[(size_t)r0 * VOCAB + c]       = o0;
            *(float2*)&out[(size_t)(r0 + 8) * VOCAB + c] = o1;
        }
    }
}

// ---------------------------------------------------------------------------
extern "C" void kernel_launch(void* const* d_in, const int* in_sizes, int n_in,
                              void* d_out, int out_size)
{
    const float* enc_out  = (const float*)d_in[0];
    const float* pred_out = (const float*)d_in[1];
    const float* W_enc    = (const float*)d_in[2];
    const float* b_enc    = (const float*)d_in[3];
    const float* W_pred   = (const float*)d_in[4];
    const float* b_pred   = (const float*)d_in[5];
    const float* W_joint  = (const float*)d_in[6];
    const float* b_joint  = (const float*)d_in[7];
    float* out = (float*)d_out;

    static bool attr_done = false;
    if (!attr_done) {
        cudaFuncSetAttribute(proj_hmma_kernel, cudaFuncAttributeMaxDynamicSharedMemorySize, HMMA_SMEM);
        cudaFuncSetAttribute(joint_kernel, cudaFuncAttributeMaxDynamicSharedMemorySize, HMMA_SMEM);
        attr_done = true;
    }

    convert_kernel<<<(CONV_TOTAL + 255) / 256, 256>>>(enc_out, pred_out, W_enc, W_pred, W_joint);
    proj_hmma_kernel<<<80, 256, HMMA_SMEM>>>(b_enc, b_pred);
    prep_a_kernel<<<(MROWS / 4) * (JDIM / 8) / 256, 256>>>();
    joint_kernel<<<(MROWS / BM) * (VOCAB / BN), 256, HMMA_SMEM>>>(b_joint, out);
}